// round 4
// baseline (speedup 1.0000x reference)
#include <cuda_runtime.h>

#define B 16
#define H0 720
#define W0 720
#define HP 359
#define WP 359
#define H2 357
#define W2 357
#define H3 355
#define W3 355

// padded row strides (16B-aligned rows, room for vector-load overreach)
#define W1P 368
#define W2P 368
#define W3P 360

__device__ __align__(128) float g_p1[B * 10 * HP * W1P];
__device__ __align__(128) float g_p2[B * 16 * H2 * W2P];
__device__ __align__(128) float g_p3[B * 32 * H3 * W3P];

typedef unsigned long long ull;

// ---------------- packed f32x2 helpers ----------------
__device__ __forceinline__ ull pack2(float a, float b) {
    ull r;
    asm("mov.b64 %0, {%1,%2};" : "=l"(r) : "f"(a), "f"(b));
    return r;
}
__device__ __forceinline__ void fma2(ull& d, ull a, ull b) {
    asm("fma.rn.f32x2 %0, %1, %2, %0;" : "+l"(d) : "l"(a), "l"(b));
}
__device__ __forceinline__ float2 unpack2(ull v) {
    float2 f;
    asm("mov.b64 {%0,%1}, %2;" : "=f"(f.x), "=f"(f.y) : "l"(v));
    return f;
}

// =====================================================================
// Kernel 1: conv1(3->10,3x3)+PReLU+maxpool, norm folded into weights.
// Thread: 2 pooled-x (4 conv-x), 5 couts (grid.z selects group of 5).
// =====================================================================
__global__ __launch_bounds__(64)
void k_conv1_pool(const float* __restrict__ x,
                  const float* __restrict__ w,
                  const float* __restrict__ bias,
                  const float* __restrict__ alpha)
{
    __shared__ ull   s_wd[135];   // 5 co x 27, scaled + duplicated
    __shared__ float s_b2[5];
    __shared__ float s_a2[5];

    int cg = blockIdx.z & 1;
    int b  = blockIdx.z >> 1;

    for (int i = threadIdx.x; i < 135; i += blockDim.x) {
        float wv = w[cg * 135 + i] * 0.0078125f;
        s_wd[i] = pack2(wv, wv);
    }
    if (threadIdx.x < 5) {
        int co = cg * 5 + threadIdx.x;
        float s = 0.f;
#pragma unroll
        for (int k = 0; k < 27; k++) s += w[co * 27 + k];
        s_b2[threadIdx.x] = bias[co] - 127.5f * 0.0078125f * s;
        s_a2[threadIdx.x] = alpha[co];
    }
    __syncthreads();

    int t = blockIdx.x * blockDim.x + threadIdx.x;
    if (t >= 180) return;
    int py = blockIdx.y;
    int iy = 2 * py;
    int x4 = 4 * t;

    ull acc[5][2][2];
#pragma unroll
    for (int co = 0; co < 5; co++) {
        float bb = s_b2[co];
        ull bp = pack2(bb, bb);
        acc[co][0][0] = bp; acc[co][0][1] = bp;
        acc[co][1][0] = bp; acc[co][1][1] = bp;
    }

#pragma unroll
    for (int ci = 0; ci < 3; ci++) {
        const float* rp = x + ((size_t)(b * 3 + ci) * H0 + iy) * W0 + x4;
        ull pr[4][5];
#pragma unroll
        for (int r = 0; r < 4; r++) {
            float4 v4 = *(const float4*)(rp + (size_t)r * W0);
            float2 v2 = make_float2(0.f, 0.f);
            if (t < 179) v2 = *(const float2*)(rp + (size_t)r * W0 + 4);
            pr[r][0] = pack2(v4.x, v4.y);
            pr[r][1] = pack2(v4.y, v4.z);
            pr[r][2] = pack2(v4.z, v4.w);
            pr[r][3] = pack2(v4.w, v2.x);
            pr[r][4] = pack2(v2.x, v2.y);
        }
#pragma unroll
        for (int co = 0; co < 5; co++) {
#pragma unroll
            for (int ky = 0; ky < 3; ky++)
#pragma unroll
                for (int kx = 0; kx < 3; kx++) {
                    ull wd = s_wd[co * 27 + ci * 9 + ky * 3 + kx];
                    fma2(acc[co][0][0], pr[ky    ][kx    ], wd);
                    fma2(acc[co][0][1], pr[ky    ][kx + 2], wd);
                    fma2(acc[co][1][0], pr[ky + 1][kx    ], wd);
                    fma2(acc[co][1][1], pr[ky + 1][kx + 2], wd);
                }
        }
    }

#pragma unroll
    for (int co = 0; co < 5; co++) {
        float a = s_a2[co];
        float2 r00 = unpack2(acc[co][0][0]);
        float2 r01 = unpack2(acc[co][0][1]);
        float2 r10 = unpack2(acc[co][1][0]);
        float2 r11 = unpack2(acc[co][1][1]);
        float p00 = r00.x >= 0.f ? r00.x : a * r00.x;
        float p01 = r00.y >= 0.f ? r00.y : a * r00.y;
        float p10 = r10.x >= 0.f ? r10.x : a * r10.x;
        float p11 = r10.y >= 0.f ? r10.y : a * r10.y;
        float q00 = r01.x >= 0.f ? r01.x : a * r01.x;
        float q01 = r01.y >= 0.f ? r01.y : a * r01.y;
        float q10 = r11.x >= 0.f ? r11.x : a * r11.x;
        float q11 = r11.y >= 0.f ? r11.y : a * r11.y;
        float m0 = fmaxf(fmaxf(p00, p01), fmaxf(p10, p11));
        float m1 = fmaxf(fmaxf(q00, q01), fmaxf(q10, q11));
        float* op = g_p1 + ((size_t)(b * 10 + cg * 5 + co) * HP + py) * W1P + 2 * t;
        *(float2*)op = make_float2(m0, m1);
    }
}

// =====================================================================
// Kernel 2: conv2 (10->16,3x3)+PReLU.  Thread: 8 couts x 4 x.
// =====================================================================
__global__ __launch_bounds__(96)
void k_conv2(const float* __restrict__ w,
             const float* __restrict__ bias,
             const float* __restrict__ alpha)
{
    __shared__ ull   s_wd[8 * 90];
    __shared__ float s_b[8];
    __shared__ float s_a[8];

    int bz = blockIdx.z;
    int b  = bz >> 1;
    int cg = bz & 1;

    for (int i = threadIdx.x; i < 720; i += blockDim.x) {
        float wv = w[cg * 720 + i];
        s_wd[i] = pack2(wv, wv);
    }
    if (threadIdx.x < 8) {
        s_b[threadIdx.x] = bias[cg * 8 + threadIdx.x];
        s_a[threadIdx.x] = alpha[cg * 8 + threadIdx.x];
    }
    __syncthreads();

    int t = threadIdx.x;
    if (t >= 90) return;
    int x0 = 4 * t;
    int py = blockIdx.y;

    ull acc[8][2];
#pragma unroll
    for (int c = 0; c < 8; c++) {
        float bb = s_b[c];
        acc[c][0] = pack2(bb, bb);
        acc[c][1] = pack2(bb, bb);
    }

#pragma unroll 1
    for (int ci = 0; ci < 10; ci++) {
        const float* p = g_p1 + ((size_t)(b * 10 + ci) * HP + py) * W1P + x0;
        ull pr[3][5];
#pragma unroll
        for (int ky = 0; ky < 3; ky++) {
            float4 v4 = *(const float4*)(p + (size_t)ky * W1P);
            float2 v2 = *(const float2*)(p + (size_t)ky * W1P + 4);
            pr[ky][0] = pack2(v4.x, v4.y);
            pr[ky][1] = pack2(v4.y, v4.z);
            pr[ky][2] = pack2(v4.z, v4.w);
            pr[ky][3] = pack2(v4.w, v2.x);
            pr[ky][4] = pack2(v2.x, v2.y);
        }
        const ull* wp = s_wd + ci * 9;
#pragma unroll
        for (int c = 0; c < 8; c++) {
#pragma unroll
            for (int ky = 0; ky < 3; ky++)
#pragma unroll
                for (int kx = 0; kx < 3; kx++) {
                    ull wd = wp[c * 90 + ky * 3 + kx];
                    fma2(acc[c][0], pr[ky][kx    ], wd);
                    fma2(acc[c][1], pr[ky][kx + 2], wd);
                }
        }
    }

#pragma unroll
    for (int c = 0; c < 8; c++) {
        float a = s_a[c];
        float2 tlo = unpack2(acc[c][0]);
        float2 thi = unpack2(acc[c][1]);
        float4 o;
        o.x = tlo.x >= 0.f ? tlo.x : a * tlo.x;
        o.y = tlo.y >= 0.f ? tlo.y : a * tlo.y;
        o.z = thi.x >= 0.f ? thi.x : a * thi.x;
        o.w = thi.y >= 0.f ? thi.y : a * thi.y;
        float* op = g_p2 + ((size_t)(b * 16 + cg * 8 + c) * H2 + py) * W2P + x0;
        *(float4*)op = o;
    }
}

// =====================================================================
// Kernel 3: conv3 (16->32,3x3)+PReLU.  Thread: 8 couts x 4 x.
// =====================================================================
__global__ __launch_bounds__(96)
void k_conv3(const float* __restrict__ w,
             const float* __restrict__ bias,
             const float* __restrict__ alpha)
{
    __shared__ ull   s_wd[8 * 144];
    __shared__ float s_b[8];
    __shared__ float s_a[8];

    int bz = blockIdx.z;
    int b  = bz >> 2;
    int cg = bz & 3;

    for (int i = threadIdx.x; i < 1152; i += blockDim.x) {
        float wv = w[cg * 1152 + i];
        s_wd[i] = pack2(wv, wv);
    }
    if (threadIdx.x < 8) {
        s_b[threadIdx.x] = bias[cg * 8 + threadIdx.x];
        s_a[threadIdx.x] = alpha[cg * 8 + threadIdx.x];
    }
    __syncthreads();

    int t = threadIdx.x;
    if (t >= 89) return;
    int x0 = 4 * t;
    int py = blockIdx.y;

    ull acc[8][2];
#pragma unroll
    for (int c = 0; c < 8; c++) {
        float bb = s_b[c];
        acc[c][0] = pack2(bb, bb);
        acc[c][1] = pack2(bb, bb);
    }

#pragma unroll 1
    for (int ci = 0; ci < 16; ci++) {
        const float* p = g_p2 + ((size_t)(b * 16 + ci) * H2 + py) * W2P + x0;
        ull pr[3][5];
#pragma unroll
        for (int ky = 0; ky < 3; ky++) {
            float4 v4 = *(const float4*)(p + (size_t)ky * W2P);
            float2 v2 = *(const float2*)(p + (size_t)ky * W2P + 4);
            pr[ky][0] = pack2(v4.x, v4.y);
            pr[ky][1] = pack2(v4.y, v4.z);
            pr[ky][2] = pack2(v4.z, v4.w);
            pr[ky][3] = pack2(v4.w, v2.x);
            pr[ky][4] = pack2(v2.x, v2.y);
        }
        const ull* wp = s_wd + ci * 9;
#pragma unroll
        for (int c = 0; c < 8; c++) {
#pragma unroll
            for (int ky = 0; ky < 3; ky++)
#pragma unroll
                for (int kx = 0; kx < 3; kx++) {
                    ull wd = wp[c * 144 + ky * 3 + kx];
                    fma2(acc[c][0], pr[ky][kx    ], wd);
                    fma2(acc[c][1], pr[ky][kx + 2], wd);
                }
        }
    }

#pragma unroll
    for (int c = 0; c < 8; c++) {
        float a = s_a[c];
        float2 tlo = unpack2(acc[c][0]);
        float2 thi = unpack2(acc[c][1]);
        float4 o;
        o.x = tlo.x >= 0.f ? tlo.x : a * tlo.x;
        o.y = tlo.y >= 0.f ? tlo.y : a * tlo.y;
        o.z = thi.x >= 0.f ? thi.x : a * thi.x;
        o.w = thi.y >= 0.f ? thi.y : a * thi.y;
        float* op = g_p3 + ((size_t)(b * 32 + cg * 8 + c) * H3 + py) * W3P + x0;
        *(float4*)op = o;
    }
}

// =====================================================================
// Kernel 4: 1x1 heads + softmax.  Thread: 4 pixels, f4 loads.
// out = [reg(16,4,355,355), prob(16,2,355,355)]
// =====================================================================
__global__ __launch_bounds__(96)
void k_heads(const float* __restrict__ w41,
             const float* __restrict__ b41,
             const float* __restrict__ w42,
             const float* __restrict__ b42,
             float* __restrict__ out)
{
    __shared__ ull s41d[64];    // [2][32] duplicated
    __shared__ ull s42d[128];   // [4][32] duplicated
    __shared__ float sb41[2];
    __shared__ float sb42[4];
    for (int i = threadIdx.x; i < 64; i += blockDim.x) s41d[i] = pack2(w41[i], w41[i]);
    for (int i = threadIdx.x; i < 128; i += blockDim.x) s42d[i] = pack2(w42[i], w42[i]);
    if (threadIdx.x < 2) sb41[threadIdx.x] = b41[threadIdx.x];
    if (threadIdx.x < 4) sb42[threadIdx.x] = b42[threadIdx.x];
    __syncthreads();

    int t = threadIdx.x;
    if (t >= 89) return;
    int x0 = 4 * t;
    int py = blockIdx.y;
    int b  = blockIdx.z;

    const float* p = g_p3 + ((size_t)(b * 32) * H3 + py) * W3P + x0;

    ull l0a, l0b, l1a, l1b;
    ull r0a, r0b, r1a, r1b, r2a, r2b, r3a, r3b;
    {
        float v = sb41[0]; l0a = pack2(v, v); l0b = l0a;
        v = sb41[1]; l1a = pack2(v, v); l1b = l1a;
        v = sb42[0]; r0a = pack2(v, v); r0b = r0a;
        v = sb42[1]; r1a = pack2(v, v); r1b = r1a;
        v = sb42[2]; r2a = pack2(v, v); r2b = r2a;
        v = sb42[3]; r3a = pack2(v, v); r3b = r3a;
    }

#pragma unroll
    for (int ci = 0; ci < 32; ci++) {
        float4 v4 = *(const float4*)(p + (size_t)ci * H3 * W3P);
        ull va = pack2(v4.x, v4.y);
        ull vb = pack2(v4.z, v4.w);
        ull w;
        w = s41d[ci];       fma2(l0a, va, w); fma2(l0b, vb, w);
        w = s41d[32 + ci];  fma2(l1a, va, w); fma2(l1b, vb, w);
        w = s42d[ci];       fma2(r0a, va, w); fma2(r0b, vb, w);
        w = s42d[32 + ci];  fma2(r1a, va, w); fma2(r1b, vb, w);
        w = s42d[64 + ci];  fma2(r2a, va, w); fma2(r2b, vb, w);
        w = s42d[96 + ci];  fma2(r3a, va, w); fma2(r3b, vb, w);
    }

    float2 L0[2] = {unpack2(l0a), unpack2(l0b)};
    float2 L1[2] = {unpack2(l1a), unpack2(l1b)};
    float2 R0[2] = {unpack2(r0a), unpack2(r0b)};
    float2 R1[2] = {unpack2(r1a), unpack2(r1b)};
    float2 R2[2] = {unpack2(r2a), unpack2(r2b)};
    float2 R3[2] = {unpack2(r3a), unpack2(r3b)};

    const size_t plane = (size_t)H3 * W3;
    const size_t PROB_OFF = (size_t)B * 4 * plane;
    size_t pixbase = (size_t)py * W3 + x0;

#pragma unroll
    for (int j = 0; j < 4; j++) {
        int xx = x0 + j;
        if (xx >= W3) break;
        int h = j >> 1;
        float l0 = (j & 1) ? L0[h].y : L0[h].x;
        float l1 = (j & 1) ? L1[h].y : L1[h].x;
        float v0 = (j & 1) ? R0[h].y : R0[h].x;
        float v1 = (j & 1) ? R1[h].y : R1[h].x;
        float v2 = (j & 1) ? R2[h].y : R2[h].x;
        float v3 = (j & 1) ? R3[h].y : R3[h].x;
        float m = fmaxf(l0, l1);
        float e0 = __expf(l0 - m), e1 = __expf(l1 - m);
        float inv = 1.0f / (e0 + e1);
        size_t pix = pixbase + j;
        out[((size_t)(b * 4 + 0)) * plane + pix] = v0;
        out[((size_t)(b * 4 + 1)) * plane + pix] = v1;
        out[((size_t)(b * 4 + 2)) * plane + pix] = v2;
        out[((size_t)(b * 4 + 3)) * plane + pix] = v3;
        out[PROB_OFF + ((size_t)(b * 2 + 0)) * plane + pix] = e0 * inv;
        out[PROB_OFF + ((size_t)(b * 2 + 1)) * plane + pix] = e1 * inv;
    }
}

extern "C" void kernel_launch(void* const* d_in, const int* in_sizes, int n_in,
                              void* d_out, int out_size)
{
    const float* x        = (const float*)d_in[0];
    const float* conv1_w  = (const float*)d_in[1];
    const float* conv1_b  = (const float*)d_in[2];
    const float* prelu1_a = (const float*)d_in[3];
    const float* conv2_w  = (const float*)d_in[4];
    const float* conv2_b  = (const float*)d_in[5];
    const float* prelu2_a = (const float*)d_in[6];
    const float* conv3_w  = (const float*)d_in[7];
    const float* conv3_b  = (const float*)d_in[8];
    const float* prelu3_a = (const float*)d_in[9];
    const float* conv41_w = (const float*)d_in[10];
    const float* conv41_b = (const float*)d_in[11];
    const float* conv42_w = (const float*)d_in[12];
    const float* conv42_b = (const float*)d_in[13];
    float* out = (float*)d_out;

    dim3 g1(3, HP, B * 2);           // 3*64=192 threads >= 180 pair-cols
    k_conv1_pool<<<g1, 64>>>(x, conv1_w, conv1_b, prelu1_a);

    dim3 g2(1, H2, B * 2);
    k_conv2<<<g2, 96>>>(conv2_w, conv2_b, prelu2_a);

    dim3 g3(1, H3, B * 4);
    k_conv3<<<g3, 96>>>(conv3_w, conv3_b, prelu3_a);

    dim3 g4(1, H3, B);
    k_heads<<<g4, 96>>>(conv41_w, conv41_b, conv42_w, conv42_b, out);
}